// round 5
// baseline (speedup 1.0000x reference)
#include <cuda_runtime.h>

#define EPSF 1e-6f

__device__ __forceinline__ int tri(int i, int j) { return i * (i + 1) / 2 + j; } // j<=i

// Compute normalized density matrix (lower-tri, 36 values) for one token row.
// r[tri(i,j)] = ((L L^T)_{ij} + (i==j)*2e-6) / (trace + eps),
// trace = sum_i (LL^T)_{ii} + 8*2e-6, L = lower-tri from params with diag clamped >= 1e-4.
__device__ __forceinline__ void density36(const float4* __restrict__ row, float r[36]) {
    float p[36];
#pragma unroll
    for (int v = 0; v < 9; v++) {
        float4 q = __ldg(row + v);
        p[4 * v + 0] = q.x; p[4 * v + 1] = q.y; p[4 * v + 2] = q.z; p[4 * v + 3] = q.w;
    }
#pragma unroll
    for (int i = 0; i < 8; i++) p[tri(i, i)] = fmaxf(p[tri(i, i)], 1e-4f);
    // rho = L L^T (lower triangle)
#pragma unroll
    for (int i = 0; i < 8; i++) {
#pragma unroll
        for (int j = 0; j <= i; j++) {
            float s = 0.f;
#pragma unroll
            for (int k = 0; k <= j; k++) s = fmaf(p[tri(i, k)], p[tri(j, k)], s);
            r[tri(i, j)] = s;
        }
    }
    float trs = 0.f;
#pragma unroll
    for (int i = 0; i < 8; i++) trs += r[tri(i, i)];
    // corr = 1e-6 always (rho = LL^T + eps*I is PD => -w.min() < 0), so diag gets eps+1e-6 = 2e-6
    float inv = __fdividef(1.f, trs + 8.f * 2e-6f + EPSF);
#pragma unroll
    for (int i = 0; i < 36; i++) r[i] *= inv;
#pragma unroll
    for (int i = 0; i < 8; i++) r[tri(i, i)] += 2e-6f * inv;
}

__global__ void __launch_bounds__(64) qcbow_kernel(
    const int* __restrict__ contexts,   // [B, S]
    const int* __restrict__ targets,    // [B]
    const float* __restrict__ emb,      // [V, 36]
    float* __restrict__ out,            // [B]
    int B, int S)
{
    int b = blockIdx.x * blockDim.x + threadIdx.x;
    if (b >= B) return;

    // ---- masked mean of context density matrices ----
    float acc[36];
#pragma unroll
    for (int i = 0; i < 36; i++) acc[i] = 0.f;
    float cnt = 0.f;

#pragma unroll 1
    for (int s = 0; s < S; s++) {
        int tok = contexts[(long long)b * S + s];
        float r[36];
        density36((const float4*)(emb + (size_t)tok * 36u), r);
        float w = (tok != 0) ? 1.f : 0.f;
        cnt += w;
#pragma unroll
        for (int i = 0; i < 36; i++) acc[i] = fmaf(r[i], w, acc[i]);
    }

    // ---- target density matrix ----
    int tt = targets[b];
    float sigma[36];
    density36((const float4*)(emb + (size_t)tt * 36u), sigma);

    // ---- A_rho = mean + eps*I ; Cholesky in place (lower C, C C^T = rho_bar + eps I) ----
    float C[36];
    {
        float invc = __fdividef(1.f, cnt);
#pragma unroll
        for (int i = 0; i < 36; i++) C[i] = acc[i] * invc;
#pragma unroll
        for (int i = 0; i < 8; i++) C[tri(i, i)] += EPSF;
#pragma unroll
        for (int j = 0; j < 8; j++) {
            float d = C[tri(j, j)];
#pragma unroll
            for (int k = 0; k < j; k++) d = fmaf(-C[tri(j, k)], C[tri(j, k)], d);
            d = sqrtf(fmaxf(d, 1e-12f));
            C[tri(j, j)] = d;
            float invd = __fdividef(1.f, d);
#pragma unroll
            for (int i = j + 1; i < 8; i++) {
                float v = C[tri(i, j)];
#pragma unroll
                for (int k = 0; k < j; k++) v = fmaf(-C[tri(i, k)], C[tri(j, k)], v);
                C[tri(i, j)] = v * invd;
            }
        }
    }

    // ---- N = C^T * sigma * C  (symmetric; eig(N) = eig((rho_bar+eps I) sigma)
    //      = singular values of sqrt_rho sigma sqrt_rho in the reference) ----
    float A[8][8];
#pragma unroll
    for (int bc = 0; bc < 8; bc++) {
        float tcol[8];
#pragma unroll
        for (int k = 0; k < 8; k++) {
            float s = 0.f;
#pragma unroll
            for (int m = 0; m < 8; m++) {
                if (m < bc) continue;                       // C[m][bc]==0 for m<bc
                float sg = (k >= m) ? sigma[tri(k, m)] : sigma[tri(m, k)];
                s = fmaf(sg, C[tri(m, bc)], s);
            }
            tcol[k] = s;
        }
#pragma unroll
        for (int a = 0; a < 8; a++) {
            if (a > bc) continue;                           // symmetric: fill a<=bc, mirror
            float s = 0.f;
#pragma unroll
            for (int k = 0; k < 8; k++) {
                if (k < a) continue;                        // C[k][a]==0 for k<a
                s = fmaf(C[tri(k, a)], tcol[k], s);
            }
            A[a][bc] = s;
            A[bc][a] = s;
        }
    }

    // ---- cyclic Jacobi, values only, 6 sweeps, fully unrolled rotations ----
#pragma unroll 1
    for (int sweep = 0; sweep < 6; sweep++) {
#pragma unroll
        for (int p = 0; p < 7; p++) {
#pragma unroll
            for (int q = p + 1; q < 8; q++) {
                float apq = A[p][q];
                float app = A[p][p], aqq = A[q][q];
                float theta = __fdividef(aqq - app, 2.f * apq);
                float t = __fdividef(1.f, fabsf(theta) + sqrtf(fmaf(theta, theta, 1.f)));
                t = copysignf(t, theta);
                bool skip = !(fabsf(apq) > 1e-30f);          // also kills NaN theta (0/0)
                t = skip ? 0.f : t;
                float c = rsqrtf(fmaf(t, t, 1.f));
                float s = t * c;
                A[p][p] = fmaf(-t, apq, app);
                A[q][q] = fmaf(t, apq, aqq);
                A[p][q] = 0.f; A[q][p] = 0.f;
#pragma unroll
                for (int k = 0; k < 8; k++) {
                    if (k == p || k == q) continue;
                    float akp = A[k][p], akq = A[k][q];
                    float np = fmaf(c, akp, -s * akq);
                    float nq = fmaf(s, akp, c * akq);
                    A[k][p] = np; A[p][k] = np;
                    A[k][q] = nq; A[q][k] = nq;
                }
            }
        }
    }

    // ---- f = sum sqrt(lambda + eps), clip, -log ----
    float f = 0.f;
#pragma unroll
    for (int i = 0; i < 8; i++) f += sqrtf(fmaxf(A[i][i], 0.f) + EPSF);
    f = fminf(f, 1.f);
    out[b] = -logf(fmaxf(f, 1e-8f));
}

extern "C" void kernel_launch(void* const* d_in, const int* in_sizes, int n_in,
                              void* d_out, int out_size) {
    const int* contexts = (const int*)d_in[0];
    const int* targets  = (const int*)d_in[1];
    const float* emb    = (const float*)d_in[2];
    float* out          = (float*)d_out;

    int B = in_sizes[1];               // targets: [B]
    int S = in_sizes[0] / B;           // contexts: [B, S]

    int threads = 64;
    int blocks = (B + threads - 1) / threads;
    qcbow_kernel<<<blocks, threads>>>(contexts, targets, emb, out, B, S);
}